// round 7
// baseline (speedup 1.0000x reference)
#include <cuda_runtime.h>
#include <cstdint>

#define N_NODES 100000
#define N_EDGES 3200000
#define DIM 64
#define CAP 128
#define CAP_SHIFT 7
#define PAD 66   // 4*66=264 (mod32=8): warp's 4 S/P rows hit banks +0,+8,+16,+24 -> conflict-free

// Scratch (device globals: no allocation allowed).
__device__ float4 g_hbuf[2][(size_t)N_NODES * 16];
__device__ float4 g_hn[(size_t)N_NODES * 16];
__device__ int    g_cnt[N_NODES];
__device__ int2   g_edge[(size_t)N_NODES * CAP];

// ---------------- Bucketed edge build ----------------

__global__ void zero_int_kernel(int* __restrict__ p, int n) {
    int i = blockIdx.x * blockDim.x + threadIdx.x;
    if (i < n) p[i] = 0;
}

__global__ void scatter_kernel(const int* __restrict__ src, const int* __restrict__ dst,
                               const float* __restrict__ a,
                               int* __restrict__ cnt, int2* __restrict__ edge, int ne) {
    int e0 = (blockIdx.x * blockDim.x + threadIdx.x) * 16;
    if (e0 + 16 <= ne) {
#pragma unroll
        for (int q = 0; q < 4; q++) {
            int4   d = *(const int4*)(dst + e0 + 4 * q);
            int4   s = *(const int4*)(src + e0 + 4 * q);
            float4 w = *(const float4*)(a + e0 + 4 * q);
            int p0 = atomicAdd(&cnt[d.x], 1);
            int p1 = atomicAdd(&cnt[d.y], 1);
            int p2 = atomicAdd(&cnt[d.z], 1);
            int p3 = atomicAdd(&cnt[d.w], 1);
            edge[((size_t)d.x << CAP_SHIFT) + p0] = make_int2(s.x, __float_as_int(w.x));
            edge[((size_t)d.y << CAP_SHIFT) + p1] = make_int2(s.y, __float_as_int(w.y));
            edge[((size_t)d.z << CAP_SHIFT) + p2] = make_int2(s.z, __float_as_int(w.z));
            edge[((size_t)d.w << CAP_SHIFT) + p3] = make_int2(s.w, __float_as_int(w.w));
        }
    } else {
        for (int e = e0; e < ne; e++) {
            int d = __ldg(dst + e);
            int pos = atomicAdd(&cnt[d], 1);
            edge[((size_t)d << CAP_SHIFT) + pos] =
                make_int2(__ldg(src + e), __float_as_int(__ldg(a + e)));
        }
    }
}

// ---------------- Aggregate (measured-best form, unchanged) ----------------

__global__ void aggregate_csr(const float4* __restrict__ hin,
                              const int* __restrict__ cnt,
                              const int2* __restrict__ edge,
                              float4* __restrict__ hn, int n) {
    int g = blockIdx.x * blockDim.x + threadIdx.x;
    int v = g >> 4;
    if (v >= n) return;
    int c = g & 15;
    size_t base = (size_t)v << CAP_SHIFT;
    int i = 0, end = __ldg(cnt + v);
    float4 acca = make_float4(0.f, 0.f, 0.f, 0.f);
    float4 accb = make_float4(0.f, 0.f, 0.f, 0.f);
    for (; i + 2 <= end; i += 2) {
        int2 ea = __ldg(edge + base + i);
        int2 eb = __ldg(edge + base + i + 1);
        float4 ha = __ldg(hin + ((size_t)ea.x << 4) + c);
        float4 hb = __ldg(hin + ((size_t)eb.x << 4) + c);
        float wa = __int_as_float(ea.y), wb = __int_as_float(eb.y);
        acca.x += wa * ha.x; acca.y += wa * ha.y;
        acca.z += wa * ha.z; acca.w += wa * ha.w;
        accb.x += wb * hb.x; accb.y += wb * hb.y;
        accb.z += wb * hb.z; accb.w += wb * hb.w;
    }
    if (i < end) {
        int2 ea = __ldg(edge + base + i);
        float4 ha = __ldg(hin + ((size_t)ea.x << 4) + c);
        float wa = __int_as_float(ea.y);
        acca.x += wa * ha.x; acca.y += wa * ha.y;
        acca.z += wa * ha.z; acca.w += wa * ha.w;
    }
    float4 r = make_float4(acca.x + accb.x, acca.y + accb.y,
                           acca.z + accb.z, acca.w + accb.w);
    hn[((size_t)v << 4) + c] = r;
}

// ---------------- MLP: 64-node tile, 128 threads, 8dim x 4node micro-tile ----------------

__device__ __forceinline__ void fma2(unsigned long long& acc,
                                     unsigned long long ab, unsigned long long bb) {
    asm("fma.rn.f32x2 %0, %1, %2, %0;" : "+l"(acc) : "l"(ab), "l"(bb));
}
__device__ __forceinline__ unsigned long long dup2(float s) {
    unsigned long long r;
    unsigned int u = __float_as_uint(s);
    asm("mov.b64 %0, {%1, %1};" : "=l"(r) : "r"(u));
    return r;
}
__device__ __forceinline__ float2 unpk(unsigned long long v) {
    unsigned int lo, hi;
    asm("mov.b64 {%0, %1}, %2;" : "=r"(lo), "=r"(hi) : "l"(v));
    return make_float2(__uint_as_float(lo), __uint_as_float(hi));
}

__global__ void __launch_bounds__(128, 3)
mlp_kernel(const float4* __restrict__ hin,
           const float4* __restrict__ hn,
           const float4* __restrict__ W1,
           const float*  __restrict__ b1,
           const float4* __restrict__ W2,
           const float*  __restrict__ b2,
           float4* __restrict__ hout,
           float*  __restrict__ out,
           int out_off, int n, int write_x) {
    extern __shared__ float sm[];
    float* Ssh  = sm;                // [64][PAD]
    float* Psh  = Ssh + 64 * PAD;    // [64][PAD]
    float* W1sh = Psh + 64 * PAD;    // [64][64] [k][j]
    float* W2sh = W1sh + 4096;
    float* b1sh = W2sh + 4096;
    float* b2sh = b1sh + 64;

    int tid = threadIdx.x;
    int node0 = blockIdx.x << 6;

    for (int i = tid; i < 1024; i += 128) {
        ((float4*)W1sh)[i] = __ldg(W1 + i);
        ((float4*)W2sh)[i] = __ldg(W2 + i);
    }
    if (tid < 64) { b1sh[tid] = __ldg(b1 + tid); b2sh[tid] = __ldg(b2 + tid); }

    // Stage S/P (PAD=66 -> rows are 8B aligned; write as 2x float2)
    for (int i = tid; i < 1024; i += 128) {
        int nl = i >> 4, c = i & 15;
        int v = node0 + nl;
        float4 hv = make_float4(0.f, 0.f, 0.f, 0.f);
        float4 nv = make_float4(0.f, 0.f, 0.f, 0.f);
        if (v < n) {
            hv = __ldg(hin + ((size_t)v << 4) + c);
            nv = __ldg(hn  + ((size_t)v << 4) + c);
            if (write_x) *(float4*)(out + (size_t)v * 256 + (c << 2)) = hv;
        }
        float* sp = Ssh + nl * PAD + (c << 2);
        float* pp = Psh + nl * PAD + (c << 2);
        *(float2*)(sp)     = make_float2(hv.x + nv.x, hv.y + nv.y);
        *(float2*)(sp + 2) = make_float2(hv.z + nv.z, hv.w + nv.w);
        *(float2*)(pp)     = make_float2(hv.x * nv.x, hv.y * nv.y);
        *(float2*)(pp + 2) = make_float2(hv.z * nv.z, hv.w * nv.w);
    }
    __syncthreads();

    int tx = tid & 7;      // 8 output-dim groups of 8
    int ty = tid >> 3;     // 16 node groups of 4
    unsigned long long a1[4][4] = {};
    unsigned long long a2[4][4] = {};

#pragma unroll 4
    for (int k = 0; k < 64; k++) {
        const float* w1p = W1sh + (k << 6) + (tx << 3);
        const float* w2p = W2sh + (k << 6) + (tx << 3);
        ulonglong2 w1lo = *(const ulonglong2*)(w1p);
        ulonglong2 w1hi = *(const ulonglong2*)(w1p + 4);
        ulonglong2 w2lo = *(const ulonglong2*)(w2p);
        ulonglong2 w2hi = *(const ulonglong2*)(w2p + 4);
#pragma unroll
        for (int i = 0; i < 4; i++) {
            float s = Ssh[(ty * 4 + i) * PAD + k];
            float p = Psh[(ty * 4 + i) * PAD + k];
            unsigned long long ss = dup2(s), pp = dup2(p);
            fma2(a1[i][0], ss, w1lo.x);
            fma2(a1[i][1], ss, w1lo.y);
            fma2(a1[i][2], ss, w1hi.x);
            fma2(a1[i][3], ss, w1hi.y);
            fma2(a2[i][0], pp, w2lo.x);
            fma2(a2[i][1], pp, w2lo.y);
            fma2(a2[i][2], pp, w2hi.x);
            fma2(a2[i][3], pp, w2hi.y);
        }
    }

    int j0 = tx << 3;
#pragma unroll
    for (int i = 0; i < 4; i++) {
        int v = node0 + ty * 4 + i;
        if (v >= n) continue;
        float o[8];
#pragma unroll
        for (int jp = 0; jp < 4; jp++) {
            float2 e1 = unpk(a1[i][jp]);
            float2 e2 = unpk(a2[i][jp]);
            float x1 = e1.x + b1sh[j0 + 2 * jp];
            float x2 = e1.y + b1sh[j0 + 2 * jp + 1];
            float y1 = e2.x + b2sh[j0 + 2 * jp];
            float y2 = e2.y + b2sh[j0 + 2 * jp + 1];
            x1 = x1 > 0.f ? x1 : 0.01f * x1;
            x2 = x2 > 0.f ? x2 : 0.01f * x2;
            y1 = y1 > 0.f ? y1 : 0.01f * y1;
            y2 = y2 > 0.f ? y2 : 0.01f * y2;
            o[2 * jp]     = x1 + y1;
            o[2 * jp + 1] = x2 + y2;
        }
        float4 f4a = make_float4(o[0], o[1], o[2], o[3]);
        float4 f4b = make_float4(o[4], o[5], o[6], o[7]);
        hout[((size_t)v << 4) + (tx << 1)]     = f4a;
        hout[((size_t)v << 4) + (tx << 1) + 1] = f4b;
        *(float4*)(out + (size_t)v * 256 + out_off + j0)     = f4a;
        *(float4*)(out + (size_t)v * 256 + out_off + j0 + 4) = f4b;
    }
}

extern "C" void kernel_launch(void* const* d_in, const int* in_sizes, int n_in,
                              void* d_out, int out_size) {
    const float* x   = (const float*)d_in[0];
    const float* a   = (const float*)d_in[1];
    const float* W1s = (const float*)d_in[2];
    const float* b1s = (const float*)d_in[3];
    const float* W2s = (const float*)d_in[4];
    const float* b2s = (const float*)d_in[5];
    const int*   src = (const int*)d_in[6];
    const int*   dst = (const int*)d_in[7];
    float* out = (float*)d_out;

    int n   = in_sizes[0] / DIM;
    int ne  = in_sizes[6];
    int n16 = n * 16;

    void* p;
    cudaGetSymbolAddress(&p, g_hbuf);  float4* hbuf = (float4*)p;
    cudaGetSymbolAddress(&p, g_hn);    float4* hn   = (float4*)p;
    cudaGetSymbolAddress(&p, g_cnt);   int*    cnt  = (int*)p;
    cudaGetSymbolAddress(&p, g_edge);  int2*   edge = (int2*)p;

    const int SMEM = (64 * PAD * 2 + 4096 * 2 + 128) * 4;  // 67,072 B
    cudaFuncSetAttribute(mlp_kernel, cudaFuncAttributeMaxDynamicSharedMemorySize, SMEM);

    zero_int_kernel<<<(n + 1023) / 1024, 1024>>>(cnt, n);
    int sb = (ne / 16 + 255) / 256 + 1;
    scatter_kernel<<<sb, 256>>>(src, dst, a, cnt, edge, ne);

    const float4* hin = (const float4*)x;
    int mlp_blocks = (n + 63) / 64;
    for (int l = 0; l < 3; l++) {
        float4* hout = hbuf + (size_t)(l & 1) * ((size_t)N_NODES * 16);

        aggregate_csr<<<(n16 + 255) / 256, 256>>>(hin, cnt, edge, hn, n);

        mlp_kernel<<<mlp_blocks, 128, SMEM>>>(
            hin, hn,
            (const float4*)(W1s + (size_t)l * 4096), b1s + l * 64,
            (const float4*)(W2s + (size_t)l * 4096), b2s + l * 64,
            hout, out, DIM * (l + 1), n, l == 0 ? 1 : 0);

        hin = hout;
    }
}

// round 8
// speedup vs baseline: 1.1526x; 1.1526x over previous
#include <cuda_runtime.h>
#include <cstdint>

#define N_NODES 100000
#define N_EDGES 3200000
#define DIM 64
#define CAP 128
#define CAP_SHIFT 7

// Scratch (device globals: no allocation allowed).
__device__ float4 g_hbuf[2][(size_t)N_NODES * 16];
__device__ float4 g_hn[(size_t)N_NODES * 16];
__device__ int    g_cnt[N_NODES];
__device__ int2   g_edge[(size_t)N_NODES * CAP];

// ---------------- Bucketed edge build (R6 form) ----------------

__global__ void zero_int_kernel(int* __restrict__ p, int n) {
    int i = blockIdx.x * blockDim.x + threadIdx.x;
    if (i < n) p[i] = 0;
}

__global__ void scatter_kernel(const int* __restrict__ src, const int* __restrict__ dst,
                               const float* __restrict__ a,
                               int* __restrict__ cnt, int2* __restrict__ edge, int ne) {
    int e0 = (blockIdx.x * blockDim.x + threadIdx.x) * 8;
    if (e0 + 8 <= ne) {
        int4   d0 = *(const int4*)(dst + e0);
        int4   d1 = *(const int4*)(dst + e0 + 4);
        int4   s0 = *(const int4*)(src + e0);
        int4   s1 = *(const int4*)(src + e0 + 4);
        float4 a0 = *(const float4*)(a + e0);
        float4 a1 = *(const float4*)(a + e0 + 4);
        int p0 = atomicAdd(&cnt[d0.x], 1);
        int p1 = atomicAdd(&cnt[d0.y], 1);
        int p2 = atomicAdd(&cnt[d0.z], 1);
        int p3 = atomicAdd(&cnt[d0.w], 1);
        int p4 = atomicAdd(&cnt[d1.x], 1);
        int p5 = atomicAdd(&cnt[d1.y], 1);
        int p6 = atomicAdd(&cnt[d1.z], 1);
        int p7 = atomicAdd(&cnt[d1.w], 1);
        edge[((size_t)d0.x << CAP_SHIFT) + p0] = make_int2(s0.x, __float_as_int(a0.x));
        edge[((size_t)d0.y << CAP_SHIFT) + p1] = make_int2(s0.y, __float_as_int(a0.y));
        edge[((size_t)d0.z << CAP_SHIFT) + p2] = make_int2(s0.z, __float_as_int(a0.z));
        edge[((size_t)d0.w << CAP_SHIFT) + p3] = make_int2(s0.w, __float_as_int(a0.w));
        edge[((size_t)d1.x << CAP_SHIFT) + p4] = make_int2(s1.x, __float_as_int(a1.x));
        edge[((size_t)d1.y << CAP_SHIFT) + p5] = make_int2(s1.y, __float_as_int(a1.y));
        edge[((size_t)d1.z << CAP_SHIFT) + p6] = make_int2(s1.z, __float_as_int(a1.z));
        edge[((size_t)d1.w << CAP_SHIFT) + p7] = make_int2(s1.w, __float_as_int(a1.w));
    } else {
        for (int e = e0; e < ne; e++) {
            int d = __ldg(dst + e);
            int pos = atomicAdd(&cnt[d], 1);
            edge[((size_t)d << CAP_SHIFT) + pos] =
                make_int2(__ldg(src + e), __float_as_int(__ldg(a + e)));
        }
    }
}

// ---------------- Aggregate (R6 form, unchanged) ----------------

__global__ void aggregate_csr(const float4* __restrict__ hin,
                              const int* __restrict__ cnt,
                              const int2* __restrict__ edge,
                              float4* __restrict__ hn, int n) {
    int g = blockIdx.x * blockDim.x + threadIdx.x;
    int v = g >> 4;
    if (v >= n) return;
    int c = g & 15;
    size_t base = (size_t)v << CAP_SHIFT;
    int i = 0, end = __ldg(cnt + v);
    float4 acca = make_float4(0.f, 0.f, 0.f, 0.f);
    float4 accb = make_float4(0.f, 0.f, 0.f, 0.f);
    for (; i + 2 <= end; i += 2) {
        int2 ea = __ldg(edge + base + i);
        int2 eb = __ldg(edge + base + i + 1);
        float4 ha = __ldg(hin + ((size_t)ea.x << 4) + c);
        float4 hb = __ldg(hin + ((size_t)eb.x << 4) + c);
        float wa = __int_as_float(ea.y), wb = __int_as_float(eb.y);
        acca.x += wa * ha.x; acca.y += wa * ha.y;
        acca.z += wa * ha.z; acca.w += wa * ha.w;
        accb.x += wb * hb.x; accb.y += wb * hb.y;
        accb.z += wb * hb.z; accb.w += wb * hb.w;
    }
    if (i < end) {
        int2 ea = __ldg(edge + base + i);
        float4 ha = __ldg(hin + ((size_t)ea.x << 4) + c);
        float wa = __int_as_float(ea.y);
        acca.x += wa * ha.x; acca.y += wa * ha.y;
        acca.z += wa * ha.z; acca.w += wa * ha.w;
    }
    float4 r = make_float4(acca.x + accb.x, acca.y + accb.y,
                           acca.z + accb.z, acca.w + accb.w);
    hn[((size_t)v << 4) + c] = r;
}

// ---------------- MLP: R6 tiling, k-major transposed S/P ----------------

__device__ __forceinline__ void fma2(unsigned long long& acc,
                                     unsigned long long ab, unsigned long long bb) {
    asm("fma.rn.f32x2 %0, %1, %2, %0;" : "+l"(acc) : "l"(ab), "l"(bb));
}
__device__ __forceinline__ unsigned long long dup2(float s) {
    unsigned long long r;
    unsigned int u = __float_as_uint(s);
    asm("mov.b64 %0, {%1, %1};" : "=l"(r) : "r"(u));
    return r;
}
__device__ __forceinline__ float2 unpk(unsigned long long v) {
    unsigned int lo, hi;
    asm("mov.b64 {%0, %1}, %2;" : "=r"(lo), "=r"(hi) : "l"(v));
    return make_float2(__uint_as_float(lo), __uint_as_float(hi));
}

// 64 nodes x 64 dims per block, 256 threads, 4-node x 4-dim micro-tile.
// S/P stored k-major: S_T[k][node], row stride 68 (16B-aligned, conflict-free staging).
__global__ void __launch_bounds__(256, 3)
mlp_kernel(const float4* __restrict__ hin,
           const float4* __restrict__ hn,
           const float4* __restrict__ W1,
           const float*  __restrict__ b1,
           const float4* __restrict__ W2,
           const float*  __restrict__ b2,
           float4* __restrict__ hout,
           float*  __restrict__ out,
           int out_off, int n, int write_x) {
    extern __shared__ float sm[];
    float* ST   = sm;                // [64 k][68]  (S transposed)
    float* PT   = ST + 64 * 68;      // [64 k][68]
    float* W1sh = PT + 64 * 68;      // [64][64] [k][j]
    float* W2sh = W1sh + 4096;
    float* b1sh = W2sh + 4096;
    float* b2sh = b1sh + 64;

    int tid = threadIdx.x;
    int node0 = blockIdx.x << 6;

    for (int i = tid; i < 1024; i += 256) {
        ((float4*)W1sh)[i] = __ldg(W1 + i);
        ((float4*)W2sh)[i] = __ldg(W2 + i);
    }
    if (tid < 64) { b1sh[tid] = __ldg(b1 + tid); b2sh[tid] = __ldg(b2 + tid); }

    // Stage transposed: thread handles node nl, columns c = (tid>>6) + 4q.
    // Warp lanes span 32 consecutive nl -> scalar stores are conflict-free.
    {
        int nl = tid & 63;
        int cb = tid >> 6;            // 0..3
        int v = node0 + nl;
#pragma unroll
        for (int q = 0; q < 4; q++) {
            int c = cb + (q << 2);    // 0..15, each (nl,c) exactly once
            float4 hv = make_float4(0.f, 0.f, 0.f, 0.f);
            float4 nv = make_float4(0.f, 0.f, 0.f, 0.f);
            if (v < n) {
                hv = __ldg(hin + ((size_t)v << 4) + c);
                nv = __ldg(hn  + ((size_t)v << 4) + c);
                if (write_x) *(float4*)(out + (size_t)v * 256 + (c << 2)) = hv;
            }
            int k0 = c << 2;
            ST[(k0 + 0) * 68 + nl] = hv.x + nv.x;
            ST[(k0 + 1) * 68 + nl] = hv.y + nv.y;
            ST[(k0 + 2) * 68 + nl] = hv.z + nv.z;
            ST[(k0 + 3) * 68 + nl] = hv.w + nv.w;
            PT[(k0 + 0) * 68 + nl] = hv.x * nv.x;
            PT[(k0 + 1) * 68 + nl] = hv.y * nv.y;
            PT[(k0 + 2) * 68 + nl] = hv.z * nv.z;
            PT[(k0 + 3) * 68 + nl] = hv.w * nv.w;
        }
    }
    __syncthreads();

    int tx = tid & 15, ty = tid >> 4;   // tx: 4-dim group, ty: 4-node group
    unsigned long long a1[4][2] = {};
    unsigned long long a2[4][2] = {};

#pragma unroll 8
    for (int k = 0; k < 64; k++) {
        ulonglong2 w1 = *(const ulonglong2*)(W1sh + (k << 6) + (tx << 2));
        ulonglong2 w2 = *(const ulonglong2*)(W2sh + (k << 6) + (tx << 2));
        float4 s4 = *(const float4*)(ST + k * 68 + (ty << 2));
        float4 p4 = *(const float4*)(PT + k * 68 + (ty << 2));
        unsigned long long ss, pp;
        ss = dup2(s4.x); pp = dup2(p4.x);
        fma2(a1[0][0], ss, w1.x); fma2(a1[0][1], ss, w1.y);
        fma2(a2[0][0], pp, w2.x); fma2(a2[0][1], pp, w2.y);
        ss = dup2(s4.y); pp = dup2(p4.y);
        fma2(a1[1][0], ss, w1.x); fma2(a1[1][1], ss, w1.y);
        fma2(a2[1][0], pp, w2.x); fma2(a2[1][1], pp, w2.y);
        ss = dup2(s4.z); pp = dup2(p4.z);
        fma2(a1[2][0], ss, w1.x); fma2(a1[2][1], ss, w1.y);
        fma2(a2[2][0], pp, w2.x); fma2(a2[2][1], pp, w2.y);
        ss = dup2(s4.w); pp = dup2(p4.w);
        fma2(a1[3][0], ss, w1.x); fma2(a1[3][1], ss, w1.y);
        fma2(a2[3][0], pp, w2.x); fma2(a2[3][1], pp, w2.y);
    }

    int j0 = tx << 2;
#pragma unroll
    for (int i = 0; i < 4; i++) {
        int v = node0 + ty * 4 + i;
        if (v >= n) continue;
        float o[4];
#pragma unroll
        for (int jp = 0; jp < 2; jp++) {
            float2 e1 = unpk(a1[i][jp]);
            float2 e2 = unpk(a2[i][jp]);
            float x1 = e1.x + b1sh[j0 + 2 * jp];
            float x2 = e1.y + b1sh[j0 + 2 * jp + 1];
            float y1 = e2.x + b2sh[j0 + 2 * jp];
            float y2 = e2.y + b2sh[j0 + 2 * jp + 1];
            x1 = x1 > 0.f ? x1 : 0.01f * x1;
            x2 = x2 > 0.f ? x2 : 0.01f * x2;
            y1 = y1 > 0.f ? y1 : 0.01f * y1;
            y2 = y2 > 0.f ? y2 : 0.01f * y2;
            o[2 * jp]     = x1 + y1;
            o[2 * jp + 1] = x2 + y2;
        }
        float4 f4 = make_float4(o[0], o[1], o[2], o[3]);
        hout[((size_t)v << 4) + tx] = f4;
        *(float4*)(out + (size_t)v * 256 + out_off + j0) = f4;
    }
}

extern "C" void kernel_launch(void* const* d_in, const int* in_sizes, int n_in,
                              void* d_out, int out_size) {
    const float* x   = (const float*)d_in[0];
    const float* a   = (const float*)d_in[1];
    const float* W1s = (const float*)d_in[2];
    const float* b1s = (const float*)d_in[3];
    const float* W2s = (const float*)d_in[4];
    const float* b2s = (const float*)d_in[5];
    const int*   src = (const int*)d_in[6];
    const int*   dst = (const int*)d_in[7];
    float* out = (float*)d_out;

    int n   = in_sizes[0] / DIM;
    int ne  = in_sizes[6];
    int n16 = n * 16;

    void* p;
    cudaGetSymbolAddress(&p, g_hbuf);  float4* hbuf = (float4*)p;
    cudaGetSymbolAddress(&p, g_hn);    float4* hn   = (float4*)p;
    cudaGetSymbolAddress(&p, g_cnt);   int*    cnt  = (int*)p;
    cudaGetSymbolAddress(&p, g_edge);  int2*   edge = (int2*)p;

    const int SMEM = (64 * 68 * 2 + 4096 * 2 + 128) * 4;  // 68096 B
    cudaFuncSetAttribute(mlp_kernel, cudaFuncAttributeMaxDynamicSharedMemorySize, SMEM);

    zero_int_kernel<<<(n + 1023) / 1024, 1024>>>(cnt, n);
    int sb = (ne / 8 + 255) / 256 + 1;
    scatter_kernel<<<sb, 256>>>(src, dst, a, cnt, edge, ne);

    const float4* hin = (const float4*)x;
    int mlp_blocks = (n + 63) / 64;
    for (int l = 0; l < 3; l++) {
        float4* hout = hbuf + (size_t)(l & 1) * ((size_t)N_NODES * 16);

        aggregate_csr<<<(n16 + 255) / 256, 256>>>(hin, cnt, edge, hn, n);

        mlp_kernel<<<mlp_blocks, 256, SMEM>>>(
            hin, hn,
            (const float4*)(W1s + (size_t)l * 4096), b1s + l * 64,
            (const float4*)(W2s + (size_t)l * 4096), b2s + l * 64,
            hout, out, DIM * (l + 1), n, l == 0 ? 1 : 0);

        hin = hout;
    }
}

// round 9
// speedup vs baseline: 1.2604x; 1.0935x over previous
#include <cuda_runtime.h>
#include <cuda_fp16.h>
#include <cstdint>

#define N_NODES 100000
#define N_EDGES 3200000
#define DIM 64
#define CAP 128
#define CAP_SHIFT 7

// Scratch (device globals: no allocation allowed).
__device__ float4 g_hbuf[2][(size_t)N_NODES * 16];
__device__ float4 g_hn[(size_t)N_NODES * 16];
__device__ uint2  g_h16[(size_t)N_NODES * 16];   // h in fp16: node-major, 4 halves/thread-slot
__device__ int    g_cnt[N_NODES];
__device__ int2   g_edge[(size_t)N_NODES * CAP];

// ---------------- Bucketed edge build (R6 form, measured-good) ----------------

__global__ void zero_int_kernel(int* __restrict__ p, int n) {
    int i = blockIdx.x * blockDim.x + threadIdx.x;
    if (i < n) p[i] = 0;
}

__global__ void scatter_kernel(const int* __restrict__ src, const int* __restrict__ dst,
                               const float* __restrict__ a,
                               int* __restrict__ cnt, int2* __restrict__ edge, int ne) {
    int e0 = (blockIdx.x * blockDim.x + threadIdx.x) * 8;
    if (e0 + 8 <= ne) {
        int4   d0 = *(const int4*)(dst + e0);
        int4   d1 = *(const int4*)(dst + e0 + 4);
        int4   s0 = *(const int4*)(src + e0);
        int4   s1 = *(const int4*)(src + e0 + 4);
        float4 a0 = *(const float4*)(a + e0);
        float4 a1 = *(const float4*)(a + e0 + 4);
        int p0 = atomicAdd(&cnt[d0.x], 1);
        int p1 = atomicAdd(&cnt[d0.y], 1);
        int p2 = atomicAdd(&cnt[d0.z], 1);
        int p3 = atomicAdd(&cnt[d0.w], 1);
        int p4 = atomicAdd(&cnt[d1.x], 1);
        int p5 = atomicAdd(&cnt[d1.y], 1);
        int p6 = atomicAdd(&cnt[d1.z], 1);
        int p7 = atomicAdd(&cnt[d1.w], 1);
        edge[((size_t)d0.x << CAP_SHIFT) + p0] = make_int2(s0.x, __float_as_int(a0.x));
        edge[((size_t)d0.y << CAP_SHIFT) + p1] = make_int2(s0.y, __float_as_int(a0.y));
        edge[((size_t)d0.z << CAP_SHIFT) + p2] = make_int2(s0.z, __float_as_int(a0.z));
        edge[((size_t)d0.w << CAP_SHIFT) + p3] = make_int2(s0.w, __float_as_int(a0.w));
        edge[((size_t)d1.x << CAP_SHIFT) + p4] = make_int2(s1.x, __float_as_int(a1.x));
        edge[((size_t)d1.y << CAP_SHIFT) + p5] = make_int2(s1.y, __float_as_int(a1.y));
        edge[((size_t)d1.z << CAP_SHIFT) + p6] = make_int2(s1.z, __float_as_int(a1.z));
        edge[((size_t)d1.w << CAP_SHIFT) + p7] = make_int2(s1.w, __float_as_int(a1.w));
    } else {
        for (int e = e0; e < ne; e++) {
            int d = __ldg(dst + e);
            int pos = atomicAdd(&cnt[d], 1);
            edge[((size_t)d << CAP_SHIFT) + pos] =
                make_int2(__ldg(src + e), __float_as_int(__ldg(a + e)));
        }
    }
}

// x -> fp16 copy for layer-0 gather
__global__ void convert_x_kernel(const float4* __restrict__ x, uint2* __restrict__ h16, int n16) {
    int i = blockIdx.x * blockDim.x + threadIdx.x;
    if (i >= n16) return;
    float4 v = __ldg(x + i);
    half2 lo = __floats2half2_rn(v.x, v.y);
    half2 hi = __floats2half2_rn(v.z, v.w);
    h16[i] = make_uint2(*(unsigned int*)&lo, *(unsigned int*)&hi);
}

// ---------------- Aggregate: fp16 gather, fp32 accumulate ----------------
// 16 threads/node, 2-edge software pipeline.

__device__ __forceinline__ float4 h16_to_f4(uint2 r) {
    float2 lo = __half22float2(*(half2*)&r.x);
    float2 hi = __half22float2(*(half2*)&r.y);
    return make_float4(lo.x, lo.y, hi.x, hi.y);
}

__global__ void aggregate_csr(const uint2* __restrict__ h16,
                              const int* __restrict__ cnt,
                              const int2* __restrict__ edge,
                              float4* __restrict__ hn, int n) {
    int g = blockIdx.x * blockDim.x + threadIdx.x;
    int v = g >> 4;
    if (v >= n) return;
    int c = g & 15;
    size_t base = (size_t)v << CAP_SHIFT;
    int i = 0, end = __ldg(cnt + v);
    float4 acca = make_float4(0.f, 0.f, 0.f, 0.f);
    float4 accb = make_float4(0.f, 0.f, 0.f, 0.f);
    for (; i + 2 <= end; i += 2) {
        int2 ea = __ldg(edge + base + i);
        int2 eb = __ldg(edge + base + i + 1);
        uint2 ra = __ldg(h16 + ((size_t)ea.x << 4) + c);
        uint2 rb = __ldg(h16 + ((size_t)eb.x << 4) + c);
        float4 ha = h16_to_f4(ra);
        float4 hb = h16_to_f4(rb);
        float wa = __int_as_float(ea.y), wb = __int_as_float(eb.y);
        acca.x += wa * ha.x; acca.y += wa * ha.y;
        acca.z += wa * ha.z; acca.w += wa * ha.w;
        accb.x += wb * hb.x; accb.y += wb * hb.y;
        accb.z += wb * hb.z; accb.w += wb * hb.w;
    }
    if (i < end) {
        int2 ea = __ldg(edge + base + i);
        float4 ha = h16_to_f4(__ldg(h16 + ((size_t)ea.x << 4) + c));
        float wa = __int_as_float(ea.y);
        acca.x += wa * ha.x; acca.y += wa * ha.y;
        acca.z += wa * ha.z; acca.w += wa * ha.w;
    }
    float4 r = make_float4(acca.x + accb.x, acca.y + accb.y,
                           acca.z + accb.z, acca.w + accb.w);
    hn[((size_t)v << 4) + c] = r;
}

// ---------------- MLP (R6 form, measured-best; adds fp16 h write) ----------------

__device__ __forceinline__ void fma2(unsigned long long& acc,
                                     unsigned long long ab, unsigned long long bb) {
    asm("fma.rn.f32x2 %0, %1, %2, %0;" : "+l"(acc) : "l"(ab), "l"(bb));
}
__device__ __forceinline__ unsigned long long dup2(float s) {
    unsigned long long r;
    unsigned int u = __float_as_uint(s);
    asm("mov.b64 %0, {%1, %1};" : "=l"(r) : "r"(u));
    return r;
}
__device__ __forceinline__ float2 unpk(unsigned long long v) {
    unsigned int lo, hi;
    asm("mov.b64 {%0, %1}, %2;" : "=r"(lo), "=r"(hi) : "l"(v));
    return make_float2(__uint_as_float(lo), __uint_as_float(hi));
}

// 64 nodes x 64 dims per block, 256 threads, 4-node x 4-dim micro-tile (4x2 f32x2).
__global__ void __launch_bounds__(256, 3)
mlp_kernel(const float4* __restrict__ hin,
           const float4* __restrict__ hn,
           const float4* __restrict__ W1,
           const float*  __restrict__ b1,
           const float4* __restrict__ W2,
           const float*  __restrict__ b2,
           float4* __restrict__ hout,
           uint2*  __restrict__ h16out,
           float*  __restrict__ out,
           int out_off, int n, int write_x) {
    extern __shared__ float sm[];
    float* Ssh  = sm;                // [64][68]
    float* Psh  = Ssh + 64 * 68;     // [64][68]
    float* W1sh = Psh + 64 * 68;     // [64][64] [k][j]
    float* W2sh = W1sh + 4096;
    float* b1sh = W2sh + 4096;
    float* b2sh = b1sh + 64;

    int tid = threadIdx.x;
    int node0 = blockIdx.x << 6;

    for (int i = tid; i < 1024; i += 256) {
        ((float4*)W1sh)[i] = __ldg(W1 + i);
        ((float4*)W2sh)[i] = __ldg(W2 + i);
    }
    if (tid < 64) { b1sh[tid] = __ldg(b1 + tid); b2sh[tid] = __ldg(b2 + tid); }

    for (int i = tid; i < 1024; i += 256) {
        int nl = i >> 4, c = i & 15;
        int v = node0 + nl;
        float4 hv = make_float4(0.f, 0.f, 0.f, 0.f);
        float4 nv = make_float4(0.f, 0.f, 0.f, 0.f);
        if (v < n) {
            hv = __ldg(hin + ((size_t)v << 4) + c);
            nv = __ldg(hn  + ((size_t)v << 4) + c);
            if (write_x) *(float4*)(out + (size_t)v * 256 + (c << 2)) = hv;
        }
        float4 s4 = make_float4(hv.x + nv.x, hv.y + nv.y, hv.z + nv.z, hv.w + nv.w);
        float4 p4 = make_float4(hv.x * nv.x, hv.y * nv.y, hv.z * nv.z, hv.w * nv.w);
        *(float4*)(Ssh + nl * 68 + (c << 2)) = s4;
        *(float4*)(Psh + nl * 68 + (c << 2)) = p4;
    }
    __syncthreads();

    int tx = tid & 15, ty = tid >> 4;   // tx: 4-dim group, ty: 4-node group
    unsigned long long a1[4][2] = {};
    unsigned long long a2[4][2] = {};

#pragma unroll 8
    for (int k = 0; k < 64; k++) {
        ulonglong2 w1 = *(const ulonglong2*)(W1sh + (k << 6) + (tx << 2));
        ulonglong2 w2 = *(const ulonglong2*)(W2sh + (k << 6) + (tx << 2));
#pragma unroll
        for (int i = 0; i < 4; i++) {
            float s = Ssh[(ty * 4 + i) * 68 + k];
            float p = Psh[(ty * 4 + i) * 68 + k];
            unsigned long long ss = dup2(s), pp = dup2(p);
            fma2(a1[i][0], ss, w1.x);
            fma2(a1[i][1], ss, w1.y);
            fma2(a2[i][0], pp, w2.x);
            fma2(a2[i][1], pp, w2.y);
        }
    }

    int j0 = tx << 2;
#pragma unroll
    for (int i = 0; i < 4; i++) {
        int v = node0 + ty * 4 + i;
        if (v >= n) continue;
        float o[4];
#pragma unroll
        for (int jp = 0; jp < 2; jp++) {
            float2 e1 = unpk(a1[i][jp]);
            float2 e2 = unpk(a2[i][jp]);
            float x1 = e1.x + b1sh[j0 + 2 * jp];
            float x2 = e1.y + b1sh[j0 + 2 * jp + 1];
            float y1 = e2.x + b2sh[j0 + 2 * jp];
            float y2 = e2.y + b2sh[j0 + 2 * jp + 1];
            x1 = x1 > 0.f ? x1 : 0.01f * x1;
            x2 = x2 > 0.f ? x2 : 0.01f * x2;
            y1 = y1 > 0.f ? y1 : 0.01f * y1;
            y2 = y2 > 0.f ? y2 : 0.01f * y2;
            o[2 * jp]     = x1 + y1;
            o[2 * jp + 1] = x2 + y2;
        }
        float4 f4 = make_float4(o[0], o[1], o[2], o[3]);
        hout[((size_t)v << 4) + tx] = f4;
        half2 lo = __floats2half2_rn(o[0], o[1]);
        half2 hi = __floats2half2_rn(o[2], o[3]);
        h16out[((size_t)v << 4) + tx] = make_uint2(*(unsigned int*)&lo, *(unsigned int*)&hi);
        *(float4*)(out + (size_t)v * 256 + out_off + j0) = f4;
    }
}

extern "C" void kernel_launch(void* const* d_in, const int* in_sizes, int n_in,
                              void* d_out, int out_size) {
    const float* x   = (const float*)d_in[0];
    const float* a   = (const float*)d_in[1];
    const float* W1s = (const float*)d_in[2];
    const float* b1s = (const float*)d_in[3];
    const float* W2s = (const float*)d_in[4];
    const float* b2s = (const float*)d_in[5];
    const int*   src = (const int*)d_in[6];
    const int*   dst = (const int*)d_in[7];
    float* out = (float*)d_out;

    int n   = in_sizes[0] / DIM;
    int ne  = in_sizes[6];
    int n16 = n * 16;

    void* p;
    cudaGetSymbolAddress(&p, g_hbuf);  float4* hbuf = (float4*)p;
    cudaGetSymbolAddress(&p, g_hn);    float4* hn   = (float4*)p;
    cudaGetSymbolAddress(&p, g_h16);   uint2*  h16  = (uint2*)p;
    cudaGetSymbolAddress(&p, g_cnt);   int*    cnt  = (int*)p;
    cudaGetSymbolAddress(&p, g_edge);  int2*   edge = (int2*)p;

    const int SMEM = (64 * 68 * 2 + 4096 * 2 + 128) * 4;  // 68096 B
    cudaFuncSetAttribute(mlp_kernel, cudaFuncAttributeMaxDynamicSharedMemorySize, SMEM);

    // ---- Bucketed edge build ----
    zero_int_kernel<<<(n + 1023) / 1024, 1024>>>(cnt, n);
    int sb = (ne / 8 + 255) / 256 + 1;
    scatter_kernel<<<sb, 256>>>(src, dst, a, cnt, edge, ne);

    // x -> fp16 for layer-0 gather
    convert_x_kernel<<<(n16 + 255) / 256, 256>>>((const float4*)x, h16, n16);

    const float4* hin = (const float4*)x;
    int mlp_blocks = (n + 63) / 64;
    for (int l = 0; l < 3; l++) {
        float4* hout = hbuf + (size_t)(l & 1) * ((size_t)N_NODES * 16);

        aggregate_csr<<<(n16 + 255) / 256, 256>>>(h16, cnt, edge, hn, n);

        mlp_kernel<<<mlp_blocks, 256, SMEM>>>(
            hin, hn,
            (const float4*)(W1s + (size_t)l * 4096), b1s + l * 64,
            (const float4*)(W2s + (size_t)l * 4096), b2s + l * 64,
            hout, h16, out, DIM * (l + 1), n, l == 0 ? 1 : 0);

        hin = hout;
    }
}